// round 6
// baseline (speedup 1.0000x reference)
#include <cuda_runtime.h>
#include <cuda_bf16.h>

#define BS    4
#define NH    8
#define SEQ   2048
#define DK    64
#define NP    129
#define TI    2          // i-rows per block
#define PSTR2 130        // float2 stride for swT rows
#define TSTR  130        // float stride for t rows (h-major table, as in R4)
#define NT    256

// smem layout:
//   swT : float2 [32][PSTR2]      33280 B  (w transposed, k-major)
//   sq  : float  [TI][NH][DK]      4096 B
//   t   : float  [TI][NH][TSTR]    8320 B
//   dsm : int    [TI][SEQ]        16384 B  (dist rows, cp.async prefetched)
#define SWT_BYTES (32 * PSTR2 * 8)
#define SQ_BYTES  (TI * NH * DK * 4)
#define T_BYTES   (TI * NH * TSTR * 4)
#define D_BYTES   (TI * SEQ * 4)
#define SMEM_BYTES (SWT_BYTES + SQ_BYTES + T_BYTES + D_BYTES)   // 62080

__device__ __forceinline__ unsigned long long fma2(unsigned long long a,
                                                   unsigned long long b,
                                                   unsigned long long c) {
    unsigned long long d;
    asm("fma.rn.f32x2 %0, %1, %2, %3;" : "=l"(d) : "l"(a), "l"(b), "l"(c));
    return d;
}

__device__ __forceinline__ void cp_async16(void* smem_dst, const void* gsrc) {
    unsigned int sa = (unsigned int)__cvta_generic_to_shared(smem_dst);
    asm volatile("cp.async.cg.shared.global [%0], [%1], 16;\n"
                 :: "r"(sa), "l"(gsrc));
}

__global__ void __launch_bounds__(NT, 3)
fused_kernel(const float* __restrict__ q,
             const int*   __restrict__ dist,
             const float* __restrict__ w,
             float*       __restrict__ out) {
    extern __shared__ char smem_raw[];
    float2* swT = reinterpret_cast<float2*>(smem_raw);                      // [32][PSTR2]
    float*  sq  = reinterpret_cast<float*>(smem_raw + SWT_BYTES);           // [TI][NH][DK]
    float*  tsm = reinterpret_cast<float*>(smem_raw + SWT_BYTES + SQ_BYTES);// [TI][NH][TSTR]
    int*    dsm = reinterpret_cast<int*>(smem_raw + SWT_BYTES + SQ_BYTES + T_BYTES);

    const int tid = threadIdx.x;
    const int bi  = blockIdx.x;               // 0..4095
    const int b   = bi >> 10;                 // 1024 blocks per batch
    const int i0  = (bi & 1023) * TI;

    // ---- prefetch dist rows into smem (hidden behind proj)
    {
        const char* dbase = reinterpret_cast<const char*>(
            dist + (size_t)(b * SEQ + i0) * SEQ);
#pragma unroll
        for (int k = 0; k < TI * SEQ / (NT * 4); k++) {     // 4 iters of 16B
            const int slot = k * NT + tid;                  // int4 slot
            cp_async16(reinterpret_cast<char*>(dsm) + slot * 16,
                       dbase + slot * 16);
        }
        asm volatile("cp.async.commit_group;\n" ::: "memory");
    }

    // ---- load w transposed: swT[k2][p] = (w[p][2k2], w[p][2k2+1]); pad with 0
    {
        const float2* w2 = reinterpret_cast<const float2*>(w);
        for (int idx = tid; idx < 32 * PSTR2; idx += NT) {
            const int k2 = idx / PSTR2;
            const int p  = idx - k2 * PSTR2;
            float2 v = make_float2(0.f, 0.f);
            if (p < NP) v = w2[p * 32 + k2];
            swT[idx] = v;
        }
    }
    // ---- load q tile: sq[r][h][k]   (TI*NH*16 = 256 float4, one per thread)
    {
        const float4* q4 = reinterpret_cast<const float4*>(q);
        float4* sq4 = reinterpret_cast<float4*>(sq);
        const int r  = tid >> 7;
        const int h  = (tid >> 4) & 7;
        const int kq = tid & 15;
        sq4[tid] = q4[(((size_t)(b * NH + h) * SEQ) + i0 + r) * 16 + kq];
    }
    __syncthreads();

    // ---- projection: warp-quad per i-row, 2 heads per warp.
    //      warp: r = warp>>2, hh = (warp&3)*2; lane covers p {lane,+32,+64,+96,128}
    {
        const int warp = tid >> 5, lane = tid & 31;
        const int r  = warp >> 2;
        const int hh = (warp & 3) * 2;
        const float2* sqf2 = reinterpret_cast<const float2*>(sq) + (r * NH + hh) * 32;

        unsigned long long acc[2][5];
#pragma unroll
        for (int hl = 0; hl < 2; hl++)
#pragma unroll
            for (int u = 0; u < 5; u++) acc[hl][u] = 0ULL;

#pragma unroll 8
        for (int k2 = 0; k2 < 32; k2++) {
            const float2* wrow = swT + k2 * PSTR2;
            unsigned long long wv[5];
#pragma unroll
            for (int u = 0; u < 4; u++)
                wv[u] = *reinterpret_cast<const unsigned long long*>(wrow + lane + 32 * u);
            wv[4] = *reinterpret_cast<const unsigned long long*>(wrow + 128);
#pragma unroll
            for (int hl = 0; hl < 2; hl++) {
                unsigned long long qv = *reinterpret_cast<const unsigned long long*>(
                                            sqf2 + hl * 32 + k2);
#pragma unroll
                for (int u = 0; u < 5; u++)
                    acc[hl][u] = fma2(qv, wv[u], acc[hl][u]);
            }
        }

#pragma unroll
        for (int hl = 0; hl < 2; hl++) {
            float* trow = tsm + (r * NH + hh + hl) * TSTR;
#pragma unroll
            for (int u = 0; u < 4; u++) {
                float2 v = *reinterpret_cast<float2*>(&acc[hl][u]);
                trow[lane + 32 * u] = v.x + v.y;
            }
            if (lane == 0) {
                float2 v = *reinterpret_cast<float2*>(&acc[hl][4]);
                trow[128] = v.x + v.y;
            }
        }
    }
    asm volatile("cp.async.wait_group 0;\n" ::: "memory");
    __syncthreads();

    // ---- gather: out[b,h,i,j] = t[i-i0][h][min(dist,128)]
#pragma unroll
    for (int il = 0; il < TI; il++) {
        const int4*  drow = reinterpret_cast<const int4*>(dsm + il * SEQ);
        const float* ti   = tsm + il * (NH * TSTR);
#pragma unroll
        for (int rep = 0; rep < 2; rep++) {
            const int jv = rep * NT + tid;
            const int4 d = drow[jv];
            const int pa = min(d.x, 128);
            const int pb = min(d.y, 128);
            const int pc = min(d.z, 128);
            const int pd = min(d.w, 128);
#pragma unroll
            for (int h = 0; h < NH; h++) {
                const float* th = ti + h * TSTR;
                float4 v = make_float4(th[pa], th[pb], th[pc], th[pd]);
                float4* op = reinterpret_cast<float4*>(
                    out + (((size_t)(b * NH + h) * SEQ) + i0 + il) * SEQ);
                __stcs(&op[jv], v);
            }
        }
    }
}

extern "C" void kernel_launch(void* const* d_in, const int* in_sizes, int n_in,
                              void* d_out, int out_size) {
    const float* q    = (const float*)d_in[0];
    const int*   dist = (const int*)  d_in[1];
    const float* w    = (const float*)d_in[2];
    float*       out  = (float*)d_out;

    cudaFuncSetAttribute(fused_kernel,
                         cudaFuncAttributeMaxDynamicSharedMemorySize, SMEM_BYTES);

    fused_kernel<<<BS * (SEQ / TI), NT, SMEM_BYTES>>>(q, dist, w, out);
}

// round 8
// speedup vs baseline: 1.0399x; 1.0399x over previous
#include <cuda_runtime.h>
#include <cuda_bf16.h>

#define BS    4
#define NH    8
#define SEQ   2048
#define DK    64
#define NP    129
#define TI    4
#define PSTR2 130        // float2 stride for swT rows
#define TSTR  130        // float stride for table rows
#define NT    256
#define NCONS 192        // consumer threads (warps 0-5)
#define NTILES (BS * SEQ / TI)          // 2048
#define UNITS  (TI * SEQ / 4)           // 2048 int4 units per tile

#define SWT_BYTES  (32 * PSTR2 * 8)             // 33280
#define T_FLOATS   (TI * NH * TSTR)             // 4160
#define SMEM_BYTES (SWT_BYTES + 2 * T_FLOATS * 4)  // 66560

typedef unsigned long long ull;

__device__ __forceinline__ ull fma2(ull a, ull b, ull c) {
    ull d;
    asm("fma.rn.f32x2 %0, %1, %2, %3;" : "=l"(d) : "l"(a), "l"(b), "l"(c));
    return d;
}
__device__ __forceinline__ ull pack2(float x, float y) {
    ull r;
    asm("mov.b64 %0, {%1, %2};" : "=l"(r) : "f"(x), "f"(y));
    return r;
}
__device__ __forceinline__ void bar_sync(int id) {
    asm volatile("bar.sync %0, %1;" :: "r"(id), "r"(NT) : "memory");
}
__device__ __forceinline__ void bar_arrive(int id) {
    asm volatile("bar.arrive %0, %1;" :: "r"(id), "r"(NT) : "memory");
}

__global__ void __launch_bounds__(NT, 3)
fused_kernel(const float* __restrict__ q,
             const int*   __restrict__ dist,
             const float* __restrict__ w,
             float*       __restrict__ out) {
    extern __shared__ char smem_raw[];
    float2* swT = reinterpret_cast<float2*>(smem_raw);                 // [32][PSTR2]
    float*  tsm = reinterpret_cast<float*>(smem_raw + SWT_BYTES);      // [2][T_FLOATS]

    const int tid  = threadIdx.x;
    const int wid  = tid >> 5;
    const int lane = tid & 31;

    // ---- one-time: load w transposed (k-major): swT[k2][p]
    {
        const float2* w2 = reinterpret_cast<const float2*>(w);
        for (int idx = tid; idx < 32 * PSTR2; idx += NT) {
            const int k2 = idx / PSTR2;
            const int p  = idx - k2 * PSTR2;
            float2 v = make_float2(0.f, 0.f);
            if (p < NP) v = w2[p * 32 + k2];
            swT[idx] = v;
        }
    }
    __syncthreads();

    if (wid >= 6) {
        // ================= PRODUCER (warps 6,7) =================
        const int wp = wid - 6;      // 0 or 1: passes [wp*16, wp*16+16)
        int k = 0;
        for (int tile = blockIdx.x; tile < NTILES; tile += gridDim.x, k++) {
            const int buf = k & 1;
            if (k >= 2) bar_sync(3 + buf);          // wait table buf free

            const int b  = tile >> 9;
            const int i0 = (tile & 511) * TI;
            float* tbuf = tsm + buf * T_FLOATS;

#pragma unroll
            for (int half = 0; half < 2; half++) {
                // prefetch 8 q rows (this warp's passes), one float2 per lane
                float2 q2[8];
#pragma unroll
                for (int j = 0; j < 8; j++) {
                    const int p = wp * 16 + half * 8 + j;
                    const int r = p >> 3, h = p & 7;
                    const float2* qrow = reinterpret_cast<const float2*>(
                        q + ((size_t)(b * NH + h) * SEQ + i0 + r) * DK);
                    q2[j] = __ldcs(qrow + lane);
                }
#pragma unroll
                for (int j = 0; j < 8; j++) {
                    const int p = wp * 16 + half * 8 + j;
                    const int r = p >> 3, h = p & 7;
                    ull acc[5] = {0ULL, 0ULL, 0ULL, 0ULL, 0ULL};
#pragma unroll 8
                    for (int k2 = 0; k2 < 32; k2++) {
                        const float qx = __shfl_sync(0xffffffffu, q2[j].x, k2);
                        const float qy = __shfl_sync(0xffffffffu, q2[j].y, k2);
                        const ull qv = pack2(qx, qy);
                        const float2* wrow = swT + k2 * PSTR2;
                        ull wv[5];
#pragma unroll
                        for (int u = 0; u < 4; u++)
                            wv[u] = *reinterpret_cast<const ull*>(wrow + lane + 32 * u);
                        wv[4] = *reinterpret_cast<const ull*>(wrow + 128);
#pragma unroll
                        for (int u = 0; u < 5; u++)
                            acc[u] = fma2(qv, wv[u], acc[u]);
                    }
                    float* trow = tbuf + (r * NH + h) * TSTR;
#pragma unroll
                    for (int u = 0; u < 4; u++) {
                        float2 v = *reinterpret_cast<float2*>(&acc[u]);
                        trow[lane + 32 * u] = v.x + v.y;
                    }
                    if (lane == 0) {
                        float2 v = *reinterpret_cast<float2*>(&acc[4]);
                        trow[128] = v.x + v.y;
                    }
                }
            }
            __threadfence_block();
            bar_arrive(1 + buf);                    // publish table buf
        }
    } else {
        // ================= CONSUMER (warps 0-5) =================
        const int gtid = tid;                       // 0..191
        int k = 0;
        for (int tile = blockIdx.x; tile < NTILES; tile += gridDim.x, k++) {
            const int buf = k & 1;
            bar_sync(1 + buf);                      // wait table ready

            const int b  = tile >> 9;
            const int i0 = (tile & 511) * TI;
            const float* tbuf = tsm + buf * T_FLOATS;

            const int4* dist4 = reinterpret_cast<const int4*>(dist);
            float4*     out4  = reinterpret_cast<float4*>(out);
            const size_t dbase = ((size_t)b * SEQ + i0) * 512;           // int4 units
            const size_t obase = ((size_t)b * NH * SEQ + i0) * 512;      // float4 units
            const size_t HS4   = (size_t)SEQ * 512;                      // h stride

            int idx = gtid;
            int4 dcur = __ldcs(&dist4[dbase + (idx >> 9) * 512 + (idx & 511)]);

            for (int u = 0; u < 11; u++) {
                const int nidx = idx + NCONS;
                int4 dnxt;
                if (nidx < UNITS)
                    dnxt = __ldcs(&dist4[dbase + (nidx >> 9) * 512 + (nidx & 511)]);

                if (idx < UNITS) {
                    const int il = idx >> 9;
                    const int jv = idx & 511;
                    const int pa = min(dcur.x, 128);
                    const int pb = min(dcur.y, 128);
                    const int pc = min(dcur.z, 128);
                    const int pd = min(dcur.w, 128);
                    const float* ti = tbuf + il * (NH * TSTR);
                    const size_t ob = obase + (size_t)il * 512 + jv;
#pragma unroll
                    for (int h = 0; h < NH; h++) {
                        const float* th = ti + h * TSTR;
                        float4 v = make_float4(th[pa], th[pb], th[pc], th[pd]);
                        __stcs(&out4[ob + h * HS4], v);
                    }
                }
                idx = nidx;
                dcur = dnxt;
            }
            bar_arrive(3 + buf);                    // release table buf
        }
    }
}

extern "C" void kernel_launch(void* const* d_in, const int* in_sizes, int n_in,
                              void* d_out, int out_size) {
    const float* q    = (const float*)d_in[0];
    const int*   dist = (const int*)  d_in[1];
    const float* w    = (const float*)d_in[2];
    float*       out  = (float*)d_out;

    cudaFuncSetAttribute(fused_kernel,
                         cudaFuncAttributeMaxDynamicSharedMemorySize, SMEM_BYTES);

    int dev = 0, nsm = 148;
    cudaGetDevice(&dev);
    cudaDeviceGetAttribute(&nsm, cudaDevAttrMultiProcessorCount, dev);

    fused_kernel<<<nsm * 3, NT, SMEM_BYTES>>>(q, dist, w, out);
}

// round 10
// speedup vs baseline: 1.2546x; 1.2065x over previous
#include <cuda_runtime.h>
#include <cuda_bf16.h>

#define BS    4
#define NH    8
#define SEQ   2048
#define DK    64
#define NP    129
#define TI    8          // i-rows per block
#define PSTR2 130        // float2 stride for swT rows
#define TSTR  130        // float stride for t rows
#define NT    512

// smem:
//   swT : float2 [32][PSTR2]      33280 B  (w transposed, k-major)
//   sq  : float  [TI][NH][DK]     16384 B
//   t   : float  [TI][NH][TSTR]   33280 B
#define SWT_BYTES (32 * PSTR2 * 8)
#define SQ_BYTES  (TI * NH * DK * 4)
#define T_BYTES   (TI * NH * TSTR * 4)
#define SMEM_BYTES (SWT_BYTES + SQ_BYTES + T_BYTES)   // 82944

typedef unsigned long long ull;

__device__ __forceinline__ ull fma2(ull a, ull b, ull c) {
    ull d;
    asm("fma.rn.f32x2 %0, %1, %2, %3;" : "=l"(d) : "l"(a), "l"(b), "l"(c));
    return d;
}

__global__ void __launch_bounds__(NT, 2)
fused_kernel(const float* __restrict__ q,
             const int*   __restrict__ dist,
             const float* __restrict__ w,
             float*       __restrict__ out) {
    extern __shared__ char smem_raw[];
    float2* swT = reinterpret_cast<float2*>(smem_raw);                       // [32][PSTR2]
    float*  sq  = reinterpret_cast<float*>(smem_raw + SWT_BYTES);            // [TI][NH][DK]
    float*  tsm = reinterpret_cast<float*>(smem_raw + SWT_BYTES + SQ_BYTES); // [TI][NH][TSTR]

    const int tid = threadIdx.x;
    const int bi  = blockIdx.x;              // 0..1023
    const int b   = bi >> 8;                 // 256 blocks per batch
    const int i0  = (bi & 255) * TI;

    // ---- load w transposed: swT[k2][p] = (w[p][2k2], w[p][2k2+1]); pad with 0
    {
        const float2* w2 = reinterpret_cast<const float2*>(w);
        for (int idx = tid; idx < 32 * PSTR2; idx += NT) {
            const int k2 = idx / PSTR2;
            const int p  = idx - k2 * PSTR2;
            float2 v = make_float2(0.f, 0.f);
            if (p < NP) v = w2[p * 32 + k2];
            swT[idx] = v;
        }
    }
    // ---- load q tile: sq[r][h][k]  (TI*NH*16 = 1024 float4)
    {
        const float4* q4 = reinterpret_cast<const float4*>(q);
        float4* sq4 = reinterpret_cast<float4*>(sq);
        for (int idx = tid; idx < TI * NH * 16; idx += NT) {
            const int r  = idx >> 7;             // /128
            const int h  = (idx >> 4) & 7;
            const int kq = idx & 15;
            sq4[idx] = q4[(((size_t)(b * NH + h) * SEQ) + i0 + r) * 16 + kq];
        }
    }
    __syncthreads();

    // ---- projection: 16 warps = 8 rows x 2 p-halves; 8 heads per warp.
    //      warp (r = wid>>1, ph = wid&1) covers p in {lane+32ph, lane+64+32ph}
    {
        const int wid = tid >> 5, lane = tid & 31;
        const int r  = wid >> 1;
        const int ph = wid & 1;
        const int p0 = lane + ph * 32;           // and p0 + 64
        const float2* sqf2 = reinterpret_cast<const float2*>(sq) + r * (NH * 32);

        ull acc[NH][2];
#pragma unroll
        for (int h = 0; h < NH; h++) { acc[h][0] = 0ULL; acc[h][1] = 0ULL; }

#pragma unroll 8
        for (int k2 = 0; k2 < 32; k2++) {
            const float2* wrow = swT + k2 * PSTR2;
            const ull wv0 = *reinterpret_cast<const ull*>(wrow + p0);
            const ull wv1 = *reinterpret_cast<const ull*>(wrow + p0 + 64);
#pragma unroll
            for (int h = 0; h < NH; h++) {
                const ull qv = *reinterpret_cast<const ull*>(sqf2 + h * 32 + k2);
                acc[h][0] = fma2(qv, wv0, acc[h][0]);
                acc[h][1] = fma2(qv, wv1, acc[h][1]);
            }
        }

#pragma unroll
        for (int h = 0; h < NH; h++) {
            float* trow = tsm + (r * NH + h) * TSTR;
            float2 v0 = *reinterpret_cast<float2*>(&acc[h][0]);
            float2 v1 = *reinterpret_cast<float2*>(&acc[h][1]);
            trow[p0]      = v0.x + v0.y;
            trow[p0 + 64] = v1.x + v1.y;
        }

        // p = 128 epilogue: 64 (row,head) dot products, 4 per warp, shfl reduce
        const float2 wq = swT[lane * PSTR2 + 128];
#pragma unroll
        for (int j = 0; j < 4; j++) {
            const int pr = wid * 4 + j;
            const int rr = pr >> 3, hh = pr & 7;
            const float2 qq = *(reinterpret_cast<const float2*>(sq) + (rr * NH + hh) * 32 + lane);
            float v = qq.x * wq.x + qq.y * wq.y;
#pragma unroll
            for (int o = 16; o > 0; o >>= 1)
                v += __shfl_xor_sync(0xffffffffu, v, o);
            if (lane == 0)
                tsm[(rr * NH + hh) * TSTR + 128] = v;
        }
    }
    __syncthreads();

    // ---- gather: out[b,h,i,j] = t[i-i0][h][min(dist,128)]
    //      one int4 per thread per il; depth-4 dist prefetch ring
    {
        const int4* dist4 = reinterpret_cast<const int4*>(
            dist + ((size_t)(b * SEQ + i0)) * SEQ);
        float4* out4 = reinterpret_cast<float4*>(
            out + ((size_t)b * NH * SEQ + i0) * SEQ);
        const size_t HS4 = (size_t)SEQ * (SEQ / 4);     // h stride in float4

        int4 dv[4];
#pragma unroll
        for (int il = 0; il < 4; il++)
            dv[il] = __ldcs(&dist4[il * (SEQ / 4) + tid]);

#pragma unroll
        for (int il = 0; il < TI; il++) {
            const int4 d = dv[il & 3];
            if (il + 4 < TI)
                dv[il & 3] = __ldcs(&dist4[(il + 4) * (SEQ / 4) + tid]);

            const int pa = min(d.x, 128);
            const int pb = min(d.y, 128);
            const int pc = min(d.z, 128);
            const int pd = min(d.w, 128);
            const float* ti = tsm + il * (NH * TSTR);
            const size_t ob = (size_t)il * (SEQ / 4) + tid;
#pragma unroll
            for (int h = 0; h < NH; h++) {
                const float* th = ti + h * TSTR;
                float4 v = make_float4(th[pa], th[pb], th[pc], th[pd]);
                __stcs(&out4[ob + h * HS4], v);
            }
        }
    }
}

extern "C" void kernel_launch(void* const* d_in, const int* in_sizes, int n_in,
                              void* d_out, int out_size) {
    const float* q    = (const float*)d_in[0];
    const int*   dist = (const int*)  d_in[1];
    const float* w    = (const float*)d_in[2];
    float*       out  = (float*)d_out;

    cudaFuncSetAttribute(fused_kernel,
                         cudaFuncAttributeMaxDynamicSharedMemorySize, SMEM_BYTES);

    fused_kernel<<<BS * (SEQ / TI), NT, SMEM_BYTES>>>(q, dist, w, out);
}